// round 1
// baseline (speedup 1.0000x reference)
#include <cuda_runtime.h>
#include <cstdint>

// ---------------------------------------------------------------------------
// GCN 3-layer encoder.
//   norm   = dinv[src]*dinv[dst],  dinv = deg^-1/2, deg includes self-loop
//   layer: H = A_in @ W ;  Agg = b + H*dinv^2 (self loop)  ; Agg[dst] += H[src]*norm
//   ReLU fused into next layer's GEMM input load.
// ---------------------------------------------------------------------------

#define MAX_NODES 100000
#define MAX_EDGES 1000000

// Scratch (static __device__ arrays: allocation-free per harness rules)
__device__ float g_H  [(size_t)MAX_NODES * 128];
__device__ float g_A  [(size_t)MAX_NODES * 128];
__device__ float g_deg [MAX_NODES];
__device__ float g_dinv[MAX_NODES];
__device__ float g_norm[MAX_EDGES];

// ---------------------------------------------------------------------------
// Degree / normalization kernels
// ---------------------------------------------------------------------------
__global__ void deg_init_kernel(float* __restrict__ deg, int n) {
    int i = blockIdx.x * blockDim.x + threadIdx.x;
    if (i < n) deg[i] = 1.0f;   // self loop
}

__global__ void deg_count_kernel(const int* __restrict__ dst, float* __restrict__ deg, int m) {
    int e = blockIdx.x * blockDim.x + threadIdx.x;
    if (e < m) atomicAdd(&deg[dst[e]], 1.0f);
}

__global__ void dinv_kernel(const float* __restrict__ deg, float* __restrict__ dinv, int n) {
    int i = blockIdx.x * blockDim.x + threadIdx.x;
    if (i < n) dinv[i] = rsqrtf(deg[i]);   // deg >= 1 always (self loop)
}

__global__ void norm_kernel(const int* __restrict__ src, const int* __restrict__ dst,
                            const float* __restrict__ dinv, float* __restrict__ nrm, int m) {
    int e = blockIdx.x * blockDim.x + threadIdx.x;
    if (e < m) nrm[e] = dinv[src[e]] * dinv[dst[e]];
}

// ---------------------------------------------------------------------------
// SGEMM: C[M,F] = op(A[M,K]) @ B[K,F],  op = relu if RELU.
// BM=128, BN=64, BK=16, TM=8, TN=8, 128 threads/block.
// FMA:smem-byte ratio = 64 FMA / 64 B per thread per k-step = 1.0 (balanced).
// ---------------------------------------------------------------------------
template <int RELU>
__global__ __launch_bounds__(128)
void sgemm_kernel(const float* __restrict__ A, const float* __restrict__ B,
                  float* __restrict__ C, int M, int K, int F) {
    constexpr int BM = 128, BN = 64, BK = 16, TM = 8, TN = 8;
    __shared__ float As[BK][BM + 4];   // transposed A tile
    __shared__ float Bs[BK][BN + 4];

    const int tid = threadIdx.x;
    const int tx = tid & 7;    // 0..7  (TN cols)
    const int ty = tid >> 3;   // 0..15 (TM rows)
    const int rowBase = blockIdx.x * BM;
    const int colBase = blockIdx.y * BN;

    float acc[TM][TN];
#pragma unroll
    for (int i = 0; i < TM; i++)
#pragma unroll
        for (int j = 0; j < TN; j++) acc[i][j] = 0.0f;

    for (int kc = 0; kc < K; kc += BK) {
        // --- load A tile (128x16 floats = 512 float4, 4 per thread) ---
#pragma unroll
        for (int i = 0; i < 4; i++) {
            int id = tid + i * 128;
            int r  = id >> 2;           // 0..127
            int k4 = (id & 3) << 2;     // 0,4,8,12
            float4 v = make_float4(0.f, 0.f, 0.f, 0.f);
            int row = rowBase + r;
            if (row < M) v = *(const float4*)&A[(size_t)row * K + kc + k4];
            if (RELU) {
                v.x = fmaxf(v.x, 0.f); v.y = fmaxf(v.y, 0.f);
                v.z = fmaxf(v.z, 0.f); v.w = fmaxf(v.w, 0.f);
            }
            As[k4 + 0][r] = v.x; As[k4 + 1][r] = v.y;
            As[k4 + 2][r] = v.z; As[k4 + 3][r] = v.w;
        }
        // --- load B tile (16x64 floats = 256 float4, 2 per thread) ---
#pragma unroll
        for (int i = 0; i < 2; i++) {
            int id = tid + i * 128;
            int kr = id >> 4;           // 0..15
            int c4 = (id & 15) << 2;    // 0..60
            float4 v = *(const float4*)&B[(size_t)(kc + kr) * F + colBase + c4];
            *(float4*)&Bs[kr][c4] = v;
        }
        __syncthreads();

#pragma unroll
        for (int kk = 0; kk < BK; kk++) {
            float4 a0 = *(const float4*)&As[kk][ty * TM];
            float4 a1 = *(const float4*)&As[kk][ty * TM + 4];
            float4 b0 = *(const float4*)&Bs[kk][tx * TN];
            float4 b1 = *(const float4*)&Bs[kk][tx * TN + 4];
            float am[8] = {a0.x, a0.y, a0.z, a0.w, a1.x, a1.y, a1.z, a1.w};
            float bn[8] = {b0.x, b0.y, b0.z, b0.w, b1.x, b1.y, b1.z, b1.w};
#pragma unroll
            for (int i = 0; i < TM; i++)
#pragma unroll
                for (int j = 0; j < TN; j++)
                    acc[i][j] = fmaf(am[i], bn[j], acc[i][j]);
        }
        __syncthreads();
    }

    // --- store ---
#pragma unroll
    for (int i = 0; i < TM; i++) {
        int row = rowBase + ty * TM + i;
        if (row < M) {
            float4 o0 = make_float4(acc[i][0], acc[i][1], acc[i][2], acc[i][3]);
            float4 o1 = make_float4(acc[i][4], acc[i][5], acc[i][6], acc[i][7]);
            float* cp = &C[(size_t)row * F + colBase + tx * TN];
            *(float4*)cp       = o0;
            *(float4*)(cp + 4) = o1;
        }
    }
}

// ---------------------------------------------------------------------------
// Agg init: Out[i] = bias + H[i] * dinv[i]^2   (self-loop term + bias)
// ---------------------------------------------------------------------------
template <int F4>
__global__ __launch_bounds__(256)
void init_agg_kernel(const float* __restrict__ H, const float* __restrict__ dinv,
                     const float* __restrict__ bias, float* __restrict__ Out, int n) {
    unsigned gid = blockIdx.x * 256u + threadIdx.x;
    int i = gid / F4;
    int c = gid % F4;
    if (i >= n) return;
    float w = dinv[i]; w *= w;
    float4 h = ((const float4*)H)[(size_t)i * F4 + c];
    float4 b = ((const float4*)bias)[c];
    float4 o;
    o.x = fmaf(h.x, w, b.x); o.y = fmaf(h.y, w, b.y);
    o.z = fmaf(h.z, w, b.z); o.w = fmaf(h.w, w, b.w);
    ((float4*)Out)[(size_t)i * F4 + c] = o;
}

// ---------------------------------------------------------------------------
// Edge scatter: Out[dst[e]] += H[src[e]] * norm[e]
// One float4 per thread; vector RED.128 to L2 (sm_90+).
// F4=32 -> one warp per edge; F4=16 -> half warp per edge.
// ---------------------------------------------------------------------------
__device__ __forceinline__ void red_add_f4(float4* p, float4 v) {
    asm volatile("red.global.add.v4.f32 [%0], {%1, %2, %3, %4};"
                 :: "l"(p), "f"(v.x), "f"(v.y), "f"(v.z), "f"(v.w)
                 : "memory");
}

template <int F4>
__global__ __launch_bounds__(256)
void scatter_kernel(const float* __restrict__ H, const int* __restrict__ src,
                    const int* __restrict__ dst, const float* __restrict__ nrm,
                    float* __restrict__ Out, int m) {
    unsigned gid = blockIdx.x * 256u + threadIdx.x;
    int e = gid / F4;
    int c = gid % F4;
    if (e >= m) return;
    int s = __ldg(&src[e]);
    int d = __ldg(&dst[e]);
    float w = __ldg(&nrm[e]);
    float4 v = ((const float4*)H)[(size_t)s * F4 + c];
    float4 r = make_float4(v.x * w, v.y * w, v.z * w, v.w * w);
    red_add_f4(((float4*)Out) + (size_t)d * F4 + c, r);
}

// ---------------------------------------------------------------------------
// Launch
// ---------------------------------------------------------------------------
extern "C" void kernel_launch(void* const* d_in, const int* in_sizes, int n_in,
                              void* d_out, int out_size) {
    const float* x  = (const float*)d_in[0];
    const int*   ei = (const int*)  d_in[1];
    const float* W1 = (const float*)d_in[2];
    const float* b1 = (const float*)d_in[3];
    const float* W2 = (const float*)d_in[4];
    const float* b2 = (const float*)d_in[5];
    const float* W3 = (const float*)d_in[6];
    const float* b3 = (const float*)d_in[7];

    const int n = in_sizes[0] / 128;   // 100000
    const int m = in_sizes[1] / 2;     // 1000000
    const int* src = ei;
    const int* dst = ei + m;

    float *H, *A, *deg, *dinv, *nrm;
    cudaGetSymbolAddress((void**)&H,    g_H);
    cudaGetSymbolAddress((void**)&A,    g_A);
    cudaGetSymbolAddress((void**)&deg,  g_deg);
    cudaGetSymbolAddress((void**)&dinv, g_dinv);
    cudaGetSymbolAddress((void**)&nrm,  g_norm);

    const int T = 256;
    // --- normalization (recomputed each launch; deterministic work) ---
    deg_init_kernel <<<(n + T - 1) / T, T>>>(deg, n);
    deg_count_kernel<<<(m + T - 1) / T, T>>>(dst, deg, m);
    dinv_kernel     <<<(n + T - 1) / T, T>>>(deg, dinv, n);
    norm_kernel     <<<(m + T - 1) / T, T>>>(src, dst, dinv, nrm, m);

    // --- layer 1: 128 -> 128 ---
    {
        dim3 grid((n + 127) / 128, 2);
        sgemm_kernel<0><<<grid, 128>>>(x, W1, H, n, 128, 128);
        unsigned gi = ((unsigned)n * 32 + T - 1) / T;
        init_agg_kernel<32><<<gi, T>>>(H, dinv, b1, A, n);
        unsigned gs = ((unsigned)m * 32 + T - 1) / T;
        scatter_kernel<32><<<gs, T>>>(H, src, dst, nrm, A, m);
    }
    // --- layer 2: 128 -> 64 (relu on input) ---
    {
        dim3 grid((n + 127) / 128, 1);
        sgemm_kernel<1><<<grid, 128>>>(A, W2, H, n, 128, 64);
        unsigned gi = ((unsigned)n * 16 + T - 1) / T;
        init_agg_kernel<16><<<gi, T>>>(H, dinv, b2, A, n);
        unsigned gs = ((unsigned)m * 16 + T - 1) / T;
        scatter_kernel<16><<<gs, T>>>(H, src, dst, nrm, A, m);
    }
    // --- layer 3: 64 -> 64 (relu on input, output straight to d_out) ---
    {
        dim3 grid((n + 127) / 128, 1);
        sgemm_kernel<1><<<grid, 128>>>(A, W3, H, n, 64, 64);
        float* out = (float*)d_out;
        unsigned gi = ((unsigned)n * 16 + T - 1) / T;
        init_agg_kernel<16><<<gi, T>>>(H, dinv, b3, out, n);
        unsigned gs = ((unsigned)m * 16 + T - 1) / T;
        scatter_kernel<16><<<gs, T>>>(H, src, dst, nrm, out, m);
    }
}

// round 2
// speedup vs baseline: 1.0128x; 1.0128x over previous
#include <cuda_runtime.h>
#include <cstdint>

// ---------------------------------------------------------------------------
// GCN 3-layer encoder, CSR-pull aggregation (no scatter atomics).
//   dinv = (deg+1)^-1/2 ; layer: H = A_in @ W
//   Agg[i] = b + dinv[i]^2*H[i] + sum_{e: dst=i} dinv[src]*dinv[i] * H[src]
//   ReLU fused into aggregation store for layers 1,2.
// ---------------------------------------------------------------------------

#define MAX_NODES 100000
#define MAX_EDGES 1000000

__device__ float              g_H   [(size_t)MAX_NODES * 128];
__device__ float              g_A   [(size_t)MAX_NODES * 128];
__device__ int                g_cnt  [MAX_NODES];
__device__ int                g_rowptr[MAX_NODES + 1];
__device__ int                g_cursor[MAX_NODES];
__device__ float              g_dinv [MAX_NODES];
__device__ unsigned long long g_esw  [MAX_EDGES];   // packed {w:f32 hi, src:i32 lo}

// ---------------------------------------------------------------------------
// CSR build
// ---------------------------------------------------------------------------
__global__ void hist_kernel(const int* __restrict__ dst, int* __restrict__ cnt, int m) {
    int e = blockIdx.x * blockDim.x + threadIdx.x;
    if (e < m) atomicAdd(&cnt[dst[e]], 1);
}

__global__ void dinv_kernel(const int* __restrict__ cnt, float* __restrict__ dinv, int n) {
    int i = blockIdx.x * blockDim.x + threadIdx.x;
    if (i < n) dinv[i] = rsqrtf((float)(cnt[i] + 1));   // +1 self loop
}

// single-block exclusive scan: rowptr + cursor copy
__global__ __launch_bounds__(1024)
void scan_kernel(const int* __restrict__ cnt, int* __restrict__ rowptr,
                 int* __restrict__ cursor, int n) {
    const int T = 1024;
    int t = threadIdx.x;
    int chunk = (n + T - 1) / T;
    int beg = t * chunk;
    int end = min(beg + chunk, n);

    int s = 0;
    for (int i = beg; i < end; i++) s += cnt[i];

    __shared__ int sums[T];
    sums[t] = s;
    __syncthreads();
    // Hillis-Steele inclusive scan
    for (int d = 1; d < T; d <<= 1) {
        int v = (t >= d) ? sums[t - d] : 0;
        __syncthreads();
        sums[t] += v;
        __syncthreads();
    }
    int run = sums[t] - s;   // exclusive prefix for this chunk
    for (int i = beg; i < end; i++) {
        rowptr[i] = run;
        cursor[i] = run;
        run += cnt[i];
    }
    if (t == T - 1) rowptr[n] = run;
}

__global__ void fill_kernel(const int* __restrict__ src, const int* __restrict__ dst,
                            const float* __restrict__ dinv, int* __restrict__ cursor,
                            unsigned long long* __restrict__ esw, int m) {
    int e = blockIdx.x * blockDim.x + threadIdx.x;
    if (e >= m) return;
    int s = src[e];
    int d = dst[e];
    float w = dinv[s] * dinv[d];
    int pos = atomicAdd(&cursor[d], 1);
    esw[pos] = ((unsigned long long)__float_as_uint(w) << 32) | (unsigned)s;
}

// ---------------------------------------------------------------------------
// SGEMM: C[M,F] = A[M,K] @ B[K,F]. BM=128, BN=64, BK=16, TM=TN=8, 128 thr.
// ---------------------------------------------------------------------------
__global__ __launch_bounds__(128)
void sgemm_kernel(const float* __restrict__ A, const float* __restrict__ B,
                  float* __restrict__ C, int M, int K, int F) {
    constexpr int BM = 128, BN = 64, BK = 16, TM = 8, TN = 8;
    __shared__ float As[BK][BM + 4];
    __shared__ float Bs[BK][BN + 4];

    const int tid = threadIdx.x;
    const int tx = tid & 7;
    const int ty = tid >> 3;
    const int rowBase = blockIdx.x * BM;
    const int colBase = blockIdx.y * BN;

    float acc[TM][TN];
#pragma unroll
    for (int i = 0; i < TM; i++)
#pragma unroll
        for (int j = 0; j < TN; j++) acc[i][j] = 0.0f;

    for (int kc = 0; kc < K; kc += BK) {
#pragma unroll
        for (int i = 0; i < 4; i++) {
            int id = tid + i * 128;
            int r  = id >> 2;
            int k4 = (id & 3) << 2;
            float4 v = make_float4(0.f, 0.f, 0.f, 0.f);
            int row = rowBase + r;
            if (row < M) v = *(const float4*)&A[(size_t)row * K + kc + k4];
            As[k4 + 0][r] = v.x; As[k4 + 1][r] = v.y;
            As[k4 + 2][r] = v.z; As[k4 + 3][r] = v.w;
        }
#pragma unroll
        for (int i = 0; i < 2; i++) {
            int id = tid + i * 128;
            int kr = id >> 4;
            int c4 = (id & 15) << 2;
            float4 v = *(const float4*)&B[(size_t)(kc + kr) * F + colBase + c4];
            *(float4*)&Bs[kr][c4] = v;
        }
        __syncthreads();

#pragma unroll
        for (int kk = 0; kk < BK; kk++) {
            float4 a0 = *(const float4*)&As[kk][ty * TM];
            float4 a1 = *(const float4*)&As[kk][ty * TM + 4];
            float4 b0 = *(const float4*)&Bs[kk][tx * TN];
            float4 b1 = *(const float4*)&Bs[kk][tx * TN + 4];
            float am[8] = {a0.x, a0.y, a0.z, a0.w, a1.x, a1.y, a1.z, a1.w};
            float bn[8] = {b0.x, b0.y, b0.z, b0.w, b1.x, b1.y, b1.z, b1.w};
#pragma unroll
            for (int i = 0; i < TM; i++)
#pragma unroll
                for (int j = 0; j < TN; j++)
                    acc[i][j] = fmaf(am[i], bn[j], acc[i][j]);
        }
        __syncthreads();
    }

#pragma unroll
    for (int i = 0; i < TM; i++) {
        int row = rowBase + ty * TM + i;
        if (row < M) {
            float4 o0 = make_float4(acc[i][0], acc[i][1], acc[i][2], acc[i][3]);
            float4 o1 = make_float4(acc[i][4], acc[i][5], acc[i][6], acc[i][7]);
            float* cp = &C[(size_t)row * F + colBase + tx * TN];
            *(float4*)cp       = o0;
            *(float4*)(cp + 4) = o1;
        }
    }
}

// ---------------------------------------------------------------------------
// CSR pull aggregation. F4 float4-lanes per node (32 for F=128, 16 for F=64).
// Out[i] = bias + dinv[i]^2*H[i] + sum_k w_k * H[s_k]; optional ReLU on store.
// ---------------------------------------------------------------------------
template <int F4, int RELU>
__global__ __launch_bounds__(256)
void aggregate_kernel(const float* __restrict__ H,
                      const int* __restrict__ rowptr,
                      const unsigned long long* __restrict__ esw,
                      const float* __restrict__ dinv,
                      const float* __restrict__ bias,
                      float* __restrict__ Out, int n) {
    constexpr int G = 256 / F4;               // nodes per block
    int i = blockIdx.x * G + (threadIdx.x / F4);
    int c = threadIdx.x % F4;
    if (i >= n) return;

    float di = dinv[i];
    float wl = di * di;
    float4 h  = ((const float4*)H)[(size_t)i * F4 + c];
    float4 b  = ((const float4*)bias)[c];
    float4 acc;
    acc.x = fmaf(h.x, wl, b.x);
    acc.y = fmaf(h.y, wl, b.y);
    acc.z = fmaf(h.z, wl, b.z);
    acc.w = fmaf(h.w, wl, b.w);

    int k   = rowptr[i];
    int end = rowptr[i + 1];

    // unroll-2 for MLP on the gather chain
    for (; k + 1 < end; k += 2) {
        unsigned long long p0 = __ldg(&esw[k]);
        unsigned long long p1 = __ldg(&esw[k + 1]);
        int   s0 = (int)(p0 & 0xffffffffu);
        int   s1 = (int)(p1 & 0xffffffffu);
        float w0 = __uint_as_float((unsigned)(p0 >> 32));
        float w1 = __uint_as_float((unsigned)(p1 >> 32));
        float4 h0 = ((const float4*)H)[(size_t)s0 * F4 + c];
        float4 h1 = ((const float4*)H)[(size_t)s1 * F4 + c];
        acc.x = fmaf(h0.x, w0, acc.x); acc.y = fmaf(h0.y, w0, acc.y);
        acc.z = fmaf(h0.z, w0, acc.z); acc.w = fmaf(h0.w, w0, acc.w);
        acc.x = fmaf(h1.x, w1, acc.x); acc.y = fmaf(h1.y, w1, acc.y);
        acc.z = fmaf(h1.z, w1, acc.z); acc.w = fmaf(h1.w, w1, acc.w);
    }
    if (k < end) {
        unsigned long long p0 = __ldg(&esw[k]);
        int   s0 = (int)(p0 & 0xffffffffu);
        float w0 = __uint_as_float((unsigned)(p0 >> 32));
        float4 h0 = ((const float4*)H)[(size_t)s0 * F4 + c];
        acc.x = fmaf(h0.x, w0, acc.x); acc.y = fmaf(h0.y, w0, acc.y);
        acc.z = fmaf(h0.z, w0, acc.z); acc.w = fmaf(h0.w, w0, acc.w);
    }

    if (RELU) {
        acc.x = fmaxf(acc.x, 0.f); acc.y = fmaxf(acc.y, 0.f);
        acc.z = fmaxf(acc.z, 0.f); acc.w = fmaxf(acc.w, 0.f);
    }
    ((float4*)Out)[(size_t)i * F4 + c] = acc;
}

// ---------------------------------------------------------------------------
// Launch
// ---------------------------------------------------------------------------
extern "C" void kernel_launch(void* const* d_in, const int* in_sizes, int n_in,
                              void* d_out, int out_size) {
    const float* x  = (const float*)d_in[0];
    const int*   ei = (const int*)  d_in[1];
    const float* W1 = (const float*)d_in[2];
    const float* b1 = (const float*)d_in[3];
    const float* W2 = (const float*)d_in[4];
    const float* b2 = (const float*)d_in[5];
    const float* W3 = (const float*)d_in[6];
    const float* b3 = (const float*)d_in[7];

    const int n = in_sizes[0] / 128;   // 100000
    const int m = in_sizes[1] / 2;     // 1000000
    const int* src = ei;
    const int* dst = ei + m;

    float *H, *A, *dinv;
    int *cnt, *rowptr, *cursor;
    unsigned long long* esw;
    cudaGetSymbolAddress((void**)&H,      g_H);
    cudaGetSymbolAddress((void**)&A,      g_A);
    cudaGetSymbolAddress((void**)&cnt,    g_cnt);
    cudaGetSymbolAddress((void**)&rowptr, g_rowptr);
    cudaGetSymbolAddress((void**)&cursor, g_cursor);
    cudaGetSymbolAddress((void**)&dinv,   g_dinv);
    cudaGetSymbolAddress((void**)&esw,    g_esw);

    const int T = 256;

    // --- CSR build (inside graph, every replay) ---
    cudaMemsetAsync(cnt, 0, (size_t)n * sizeof(int));
    hist_kernel<<<(m + T - 1) / T, T>>>(dst, cnt, m);
    dinv_kernel<<<(n + T - 1) / T, T>>>(cnt, dinv, n);
    scan_kernel<<<1, 1024>>>(cnt, rowptr, cursor, n);
    fill_kernel<<<(m + T - 1) / T, T>>>(src, dst, dinv, cursor, esw, m);

    // --- layer 1: 128 -> 128, relu fused into aggregate ---
    {
        dim3 grid((n + 127) / 128, 2);
        sgemm_kernel<<<grid, 128>>>(x, W1, H, n, 128, 128);
        aggregate_kernel<32, 1><<<(n + 7) / 8, 256>>>(H, rowptr, esw, dinv, b1, A, n);
    }
    // --- layer 2: 128 -> 64, relu fused into aggregate ---
    {
        dim3 grid((n + 127) / 128, 1);
        sgemm_kernel<<<grid, 128>>>(A, W2, H, n, 128, 64);
        aggregate_kernel<16, 1><<<(n + 15) / 16, 256>>>(H, rowptr, esw, dinv, b2, A, n);
    }
    // --- layer 3: 64 -> 64, straight to d_out ---
    {
        dim3 grid((n + 127) / 128, 1);
        sgemm_kernel<<<grid, 128>>>(A, W3, H, n, 64, 64);
        aggregate_kernel<16, 0><<<(n + 15) / 16, 256>>>(H, rowptr, esw, dinv, b3,
                                                        (float*)d_out, n);
    }
}

// round 4
// speedup vs baseline: 1.5771x; 1.5572x over previous
#include <cuda_runtime.h>
#include <cuda_bf16.h>
#include <cstdint>

// ===========================================================================
// GCN 3-layer encoder.
//  - GEMMs on tensor cores via mma.sync m16n8k16 bf16 (sm_100-safe; tcgen05
//    is 'a'-gated and unavailable under this toolchain target).
//    bf16-split: A@W ~= Ah@Bh + Ah@Bl + Al@Bh, fp32 accumulate (~1.5e-5 rel).
//  - CSR-pull aggregation (no atomics in hot path), ReLU + bias fused.
// ===========================================================================

#define MAX_NODES 100000
#define MAX_EDGES 1000000

__device__ float              g_H     [(size_t)MAX_NODES * 128];
__device__ float              g_A     [(size_t)MAX_NODES * 128];
__device__ int                g_cnt   [MAX_NODES];
__device__ int                g_rowptr[MAX_NODES + 1];
__device__ int                g_cursor[MAX_NODES];
__device__ float              g_dinv  [MAX_NODES];
__device__ unsigned long long g_esw   [MAX_EDGES];   // {w:f32 hi, src:i32 lo}
__device__ int                g_bsum  [1024];
__device__ int                g_boff  [1024];
__device__ unsigned short     g_Bhi   [128 * 128];   // W^T split hi: [n][k]
__device__ unsigned short     g_Blo   [128 * 128];   // W^T split lo: [n][k]

// ---------------------------------------------------------------------------
// helpers
// ---------------------------------------------------------------------------
__device__ __forceinline__ uint32_t smem_u32(const void* p) {
    uint32_t a;
    asm("{ .reg .u64 t; cvta.to.shared.u64 t, %1; cvt.u32.u64 %0, t; }"
        : "=r"(a) : "l"(p));
    return a;
}

__device__ __forceinline__ void ldsm_x4(uint32_t& r0, uint32_t& r1,
                                        uint32_t& r2, uint32_t& r3, uint32_t addr) {
    asm volatile("ldmatrix.sync.aligned.m8n8.x4.shared.b16 {%0,%1,%2,%3}, [%4];"
                 : "=r"(r0), "=r"(r1), "=r"(r2), "=r"(r3) : "r"(addr));
}

__device__ __forceinline__ void ldsm_x2(uint32_t& r0, uint32_t& r1, uint32_t addr) {
    asm volatile("ldmatrix.sync.aligned.m8n8.x2.shared.b16 {%0,%1}, [%2];"
                 : "=r"(r0), "=r"(r1) : "r"(addr));
}

__device__ __forceinline__ void mma_bf16(float* c, uint32_t a0, uint32_t a1,
                                         uint32_t a2, uint32_t a3,
                                         uint32_t b0, uint32_t b1) {
    asm volatile(
        "mma.sync.aligned.m16n8k16.row.col.f32.bf16.bf16.f32 "
        "{%0,%1,%2,%3}, {%4,%5,%6,%7}, {%8,%9}, {%0,%1,%2,%3};"
        : "+f"(c[0]), "+f"(c[1]), "+f"(c[2]), "+f"(c[3])
        : "r"(a0), "r"(a1), "r"(a2), "r"(a3), "r"(b0), "r"(b1));
}

// ---------------------------------------------------------------------------
// CSR build
// ---------------------------------------------------------------------------
__global__ void hist_kernel(const int* __restrict__ dst, int* __restrict__ cnt, int m) {
    int e = blockIdx.x * blockDim.x + threadIdx.x;
    if (e < m) atomicAdd(&cnt[dst[e]], 1);
}

__global__ void dinv_kernel(const int* __restrict__ cnt, float* __restrict__ dinv, int n) {
    int i = blockIdx.x * blockDim.x + threadIdx.x;
    if (i < n) dinv[i] = rsqrtf((float)(cnt[i] + 1));
}

__global__ __launch_bounds__(256)
void scan_p1_kernel(const int* __restrict__ cnt, int* __restrict__ bsum, int n) {
    __shared__ int red[256];
    int base = blockIdx.x * 1024;
    int t = threadIdx.x;
    int s = 0;
#pragma unroll
    for (int j = 0; j < 4; j++) {
        int i = base + t * 4 + j;
        if (i < n) s += cnt[i];
    }
    red[t] = s;
    __syncthreads();
    for (int d = 128; d > 0; d >>= 1) {
        if (t < d) red[t] += red[t + d];
        __syncthreads();
    }
    if (t == 0) bsum[blockIdx.x] = red[0];
}

__global__ __launch_bounds__(256)
void scan_p2_kernel(const int* __restrict__ bsum, int* __restrict__ boff,
                    int* __restrict__ rowptr, int n, int nb) {
    __shared__ int sm[256];
    int t = threadIdx.x;
    int v = (t < nb) ? bsum[t] : 0;
    sm[t] = v;
    __syncthreads();
    for (int d = 1; d < 256; d <<= 1) {
        int u = (t >= d) ? sm[t - d] : 0;
        __syncthreads();
        sm[t] += u;
        __syncthreads();
    }
    if (t < nb) boff[t] = sm[t] - v;
    if (t == 255) rowptr[n] = sm[255];
}

__global__ __launch_bounds__(256)
void scan_p3_kernel(const int* __restrict__ cnt, const int* __restrict__ boff,
                    int* __restrict__ rowptr, int* __restrict__ cursor, int n) {
    __shared__ int sm[256];
    int base = blockIdx.x * 1024;
    int t = threadIdx.x;
    int c[4];
    int s = 0;
#pragma unroll
    for (int j = 0; j < 4; j++) {
        int i = base + t * 4 + j;
        c[j] = (i < n) ? cnt[i] : 0;
        s += c[j];
    }
    sm[t] = s;
    __syncthreads();
    for (int d = 1; d < 256; d <<= 1) {
        int u = (t >= d) ? sm[t - d] : 0;
        __syncthreads();
        sm[t] += u;
        __syncthreads();
    }
    int run = boff[blockIdx.x] + sm[t] - s;
#pragma unroll
    for (int j = 0; j < 4; j++) {
        int i = base + t * 4 + j;
        if (i < n) { rowptr[i] = run; cursor[i] = run; }
        run += c[j];
    }
}

__global__ void fill_kernel(const int* __restrict__ src, const int* __restrict__ dst,
                            const float* __restrict__ dinv, int* __restrict__ cursor,
                            unsigned long long* __restrict__ esw, int m) {
    int e = blockIdx.x * blockDim.x + threadIdx.x;
    if (e >= m) return;
    int s = src[e];
    int d = dst[e];
    float w = dinv[s] * dinv[d];
    int pos = atomicAdd(&cursor[d], 1);
    esw[pos] = ((unsigned long long)__float_as_uint(w) << 32) | (unsigned)s;
}

// ---------------------------------------------------------------------------
// W prep: split fp32 W[K,N] (row-major k) into bf16 hi/lo stored TRANSPOSED
// as [n][k] row-major (k contiguous) for col-major B fragments.
// ---------------------------------------------------------------------------
template <int K, int N>
__global__ void bprep_kernel(const float* __restrict__ W,
                             unsigned short* __restrict__ hi,
                             unsigned short* __restrict__ lo) {
    int idx = blockIdx.x * 256 + threadIdx.x;   // idx = k*N + n
    if (idx >= K * N) return;
    int n = idx % N;
    int k = idx / N;
    float w = W[idx];
    __nv_bfloat16 h = __float2bfloat16(w);
    __nv_bfloat16 l = __float2bfloat16(w - __bfloat162float(h));
    hi[n * K + k] = __bfloat16_as_ushort(h);
    lo[n * K + k] = __bfloat16_as_ushort(l);
}

// ---------------------------------------------------------------------------
// Tensor-core GEMM: C[M,N] = A[M,K] @ W[K,N], 3x bf16 mma.sync passes.
// CTA: 256 threads (8 warps), BM=128, full K in smem. Warp w owns 16 rows.
// smem rows padded +16B (stride K+8 elems) -> conflict-free ldmatrix.
// ---------------------------------------------------------------------------
template <int K, int N>
__global__ __launch_bounds__(256)
void gemm_mma_kernel(const float* __restrict__ A,
                     const unsigned short* __restrict__ Bhi,
                     const unsigned short* __restrict__ Blo,
                     float* __restrict__ C, int M) {
    constexpr int SA = (K + 8) * 2;         // padded row stride, bytes
    constexpr int ABYTES = 128 * SA;
    constexpr int BBYTES = N * SA;
    extern __shared__ char smem[];
    char* sAh = smem;
    char* sAl = smem + ABYTES;
    char* sBh = smem + 2 * ABYTES;
    char* sBl = smem + 2 * ABYTES + BBYTES;

    const int tid = threadIdx.x;
    const int wid = tid >> 5;
    const int lane = tid & 31;
    const int rowBase = blockIdx.x * 128;

    // --- stage B (pre-split bf16 [n][k]) into padded smem ---
    {
        constexpr int CH = N * (K / 8);     // 16B chunks
        const uint4* bh = (const uint4*)Bhi;
        const uint4* bl = (const uint4*)Blo;
        for (int i = tid; i < CH; i += 256) {
            int r = i / (K / 8), c = i % (K / 8);
            *(uint4*)(sBh + r * SA + c * 16) = bh[i];
            *(uint4*)(sBl + r * SA + c * 16) = bl[i];
        }
    }
    // --- stage A: load fp32, split to bf16 hi/lo, padded smem ---
    {
        constexpr int F4R = K / 4;
        constexpr int RP = 256 / F4R;
        int r0 = tid / F4R;
        int c4 = tid % F4R;
        for (int r = r0; r < 128; r += RP) {
            int row = rowBase + r;
            float4 v = make_float4(0.f, 0.f, 0.f, 0.f);
            if (row < M) v = *(const float4*)&A[(size_t)row * K + c4 * 4];
            __nv_bfloat16 h0 = __float2bfloat16(v.x);
            __nv_bfloat16 h1 = __float2bfloat16(v.y);
            __nv_bfloat16 h2 = __float2bfloat16(v.z);
            __nv_bfloat16 h3 = __float2bfloat16(v.w);
            __nv_bfloat16 l0 = __float2bfloat16(v.x - __bfloat162float(h0));
            __nv_bfloat16 l1 = __float2bfloat16(v.y - __bfloat162float(h1));
            __nv_bfloat16 l2 = __float2bfloat16(v.z - __bfloat162float(h2));
            __nv_bfloat16 l3 = __float2bfloat16(v.w - __bfloat162float(h3));
            uint2 hp, lp;
            hp.x = (uint32_t)__bfloat16_as_ushort(h0) | ((uint32_t)__bfloat16_as_ushort(h1) << 16);
            hp.y = (uint32_t)__bfloat16_as_ushort(h2) | ((uint32_t)__bfloat16_as_ushort(h3) << 16);
            lp.x = (uint32_t)__bfloat16_as_ushort(l0) | ((uint32_t)__bfloat16_as_ushort(l1) << 16);
            lp.y = (uint32_t)__bfloat16_as_ushort(l2) | ((uint32_t)__bfloat16_as_ushort(l3) << 16);
            *(uint2*)(sAh + r * SA + c4 * 8) = hp;
            *(uint2*)(sAl + r * SA + c4 * 8) = lp;
        }
    }
    __syncthreads();

    // --- compute ---
    constexpr int NCH = N / 8;
    float acc[NCH][4];
#pragma unroll
    for (int i = 0; i < NCH; i++) {
        acc[i][0] = 0.f; acc[i][1] = 0.f; acc[i][2] = 0.f; acc[i][3] = 0.f;
    }

    const uint32_t aH = smem_u32(sAh);
    const uint32_t aL = smem_u32(sAl);
    const uint32_t bH = smem_u32(sBh);
    const uint32_t bL = smem_u32(sBl);
    // A frag addr: lanes 0-15 -> rows 0-15 (k lo 16B), lanes 16-31 -> rows (k hi 16B)
    const uint32_t aoff = (uint32_t)(wid * 16 + (lane & 15)) * SA + (uint32_t)(lane >> 4) * 16;
    // B frag addr (x2, lanes 0-15 used): rows n0..7 at k lo / k hi 16B
    const uint32_t boff = (uint32_t)(lane & 7) * SA + (uint32_t)((lane >> 3) & 1) * 16;

#pragma unroll
    for (int kc = 0; kc < K / 16; kc++) {
        uint32_t ah0, ah1, ah2, ah3, al0, al1, al2, al3;
        ldsm_x4(ah0, ah1, ah2, ah3, aH + aoff + kc * 32);
        ldsm_x4(al0, al1, al2, al3, aL + aoff + kc * 32);
#pragma unroll
        for (int nc = 0; nc < NCH; nc++) {
            uint32_t bo = (uint32_t)(nc * 8) * SA + boff + kc * 32;
            uint32_t bh0, bh1, bl0, bl1;
            ldsm_x2(bh0, bh1, bH + bo);
            ldsm_x2(bl0, bl1, bL + bo);
            mma_bf16(acc[nc], ah0, ah1, ah2, ah3, bh0, bh1);
            mma_bf16(acc[nc], ah0, ah1, ah2, ah3, bl0, bl1);
            mma_bf16(acc[nc], al0, al1, al2, al3, bh0, bh1);
        }
    }

    // --- epilogue ---
    int r0 = rowBase + wid * 16 + (lane >> 2);
    int c0 = (lane & 3) * 2;
#pragma unroll
    for (int nc = 0; nc < NCH; nc++) {
        if (r0 < M)
            *(float2*)&C[(size_t)r0 * N + nc * 8 + c0] = make_float2(acc[nc][0], acc[nc][1]);
        if (r0 + 8 < M)
            *(float2*)&C[(size_t)(r0 + 8) * N + nc * 8 + c0] = make_float2(acc[nc][2], acc[nc][3]);
    }
}

// ---------------------------------------------------------------------------
// CSR pull aggregation (bias + self-loop + ReLU fused).
// ---------------------------------------------------------------------------
template <int F4, int RELU>
__global__ __launch_bounds__(256)
void aggregate_kernel(const float* __restrict__ H,
                      const int* __restrict__ rowptr,
                      const unsigned long long* __restrict__ esw,
                      const float* __restrict__ dinv,
                      const float* __restrict__ bias,
                      float* __restrict__ Out, int n) {
    constexpr int G = 256 / F4;
    int i = blockIdx.x * G + (threadIdx.x / F4);
    int c = threadIdx.x % F4;
    if (i >= n) return;

    float di = dinv[i];
    float wl = di * di;
    float4 h = ((const float4*)H)[(size_t)i * F4 + c];
    float4 b = ((const float4*)bias)[c];
    float4 acc;
    acc.x = fmaf(h.x, wl, b.x);
    acc.y = fmaf(h.y, wl, b.y);
    acc.z = fmaf(h.z, wl, b.z);
    acc.w = fmaf(h.w, wl, b.w);

    int k   = rowptr[i];
    int end = rowptr[i + 1];

    for (; k + 1 < end; k += 2) {
        unsigned long long p0 = __ldg(&esw[k]);
        unsigned long long p1 = __ldg(&esw[k + 1]);
        int   s0 = (int)(p0 & 0xffffffffu);
        int   s1 = (int)(p1 & 0xffffffffu);
        float w0 = __uint_as_float((unsigned)(p0 >> 32));
        float w1 = __uint_as_float((unsigned)(p1 >> 32));
        float4 h0 = ((const float4*)H)[(size_t)s0 * F4 + c];
        float4 h1 = ((const float4*)H)[(size_t)s1 * F4 + c];
        acc.x = fmaf(h0.x, w0, acc.x); acc.y = fmaf(h0.y, w0, acc.y);
        acc.z = fmaf(h0.z, w0, acc.z); acc.w = fmaf(h0.w, w0, acc.w);
        acc.x = fmaf(h1.x, w1, acc.x); acc.y = fmaf(h1.y, w1, acc.y);
        acc.z = fmaf(h1.z, w1, acc.z); acc.w = fmaf(h1.w, w1, acc.w);
    }
    if (k < end) {
        unsigned long long p0 = __ldg(&esw[k]);
        int   s0 = (int)(p0 & 0xffffffffu);
        float w0 = __uint_as_float((unsigned)(p0 >> 32));
        float4 h0 = ((const float4*)H)[(size_t)s0 * F4 + c];
        acc.x = fmaf(h0.x, w0, acc.x); acc.y = fmaf(h0.y, w0, acc.y);
        acc.z = fmaf(h0.z, w0, acc.z); acc.w = fmaf(h0.w, w0, acc.w);
    }

    if (RELU) {
        acc.x = fmaxf(acc.x, 0.f); acc.y = fmaxf(acc.y, 0.f);
        acc.z = fmaxf(acc.z, 0.f); acc.w = fmaxf(acc.w, 0.f);
    }
    ((float4*)Out)[(size_t)i * F4 + c] = acc;
}

// ---------------------------------------------------------------------------
// Launch
// ---------------------------------------------------------------------------
extern "C" void kernel_launch(void* const* d_in, const int* in_sizes, int n_in,
                              void* d_out, int out_size) {
    const float* x  = (const float*)d_in[0];
    const int*   ei = (const int*)  d_in[1];
    const float* W1 = (const float*)d_in[2];
    const float* b1 = (const float*)d_in[3];
    const float* W2 = (const float*)d_in[4];
    const float* b2 = (const float*)d_in[5];
    const float* W3 = (const float*)d_in[6];
    const float* b3 = (const float*)d_in[7];

    const int n = in_sizes[0] / 128;   // 100000
    const int m = in_sizes[1] / 2;     // 1000000
    const int* src = ei;
    const int* dst = ei + m;

    float *H, *A, *dinv;
    int *cnt, *rowptr, *cursor, *bsum, *boff;
    unsigned long long* esw;
    unsigned short *bhi, *blo;
    cudaGetSymbolAddress((void**)&H,      g_H);
    cudaGetSymbolAddress((void**)&A,      g_A);
    cudaGetSymbolAddress((void**)&cnt,    g_cnt);
    cudaGetSymbolAddress((void**)&rowptr, g_rowptr);
    cudaGetSymbolAddress((void**)&cursor, g_cursor);
    cudaGetSymbolAddress((void**)&dinv,   g_dinv);
    cudaGetSymbolAddress((void**)&esw,    g_esw);
    cudaGetSymbolAddress((void**)&bsum,   g_bsum);
    cudaGetSymbolAddress((void**)&boff,   g_boff);
    cudaGetSymbolAddress((void**)&bhi,    g_Bhi);
    cudaGetSymbolAddress((void**)&blo,    g_Blo);

    const int T = 256;
    const int nb = (n + 1023) / 1024;

    // dynamic smem sizes: 2*A + 2*B padded images
    constexpr int S1 = 2 * (128 * (128 + 8) * 2) + 2 * (128 * (128 + 8) * 2); // 139264
    constexpr int S2 = 2 * (128 * (128 + 8) * 2) + 2 * (64  * (128 + 8) * 2); // 104448
    constexpr int S3 = 2 * (128 * (64  + 8) * 2) + 2 * (64  * (64  + 8) * 2); //  55296
    cudaFuncSetAttribute(gemm_mma_kernel<128, 128>, cudaFuncAttributeMaxDynamicSharedMemorySize, S1);
    cudaFuncSetAttribute(gemm_mma_kernel<128, 64>,  cudaFuncAttributeMaxDynamicSharedMemorySize, S2);
    cudaFuncSetAttribute(gemm_mma_kernel<64, 64>,   cudaFuncAttributeMaxDynamicSharedMemorySize, S3);

    // --- CSR build ---
    cudaMemsetAsync(cnt, 0, (size_t)n * sizeof(int));
    hist_kernel<<<(m + T - 1) / T, T>>>(dst, cnt, m);
    dinv_kernel<<<(n + T - 1) / T, T>>>(cnt, dinv, n);
    scan_p1_kernel<<<nb, 256>>>(cnt, bsum, n);
    scan_p2_kernel<<<1, 256>>>(bsum, boff, rowptr, n, nb);
    scan_p3_kernel<<<nb, 256>>>(cnt, boff, rowptr, cursor, n);
    fill_kernel<<<(m + T - 1) / T, T>>>(src, dst, dinv, cursor, esw, m);

    const int GB = (n + 127) / 128;

    // --- layer 1: 128 -> 128 ---
    bprep_kernel<128, 128><<<(128 * 128 + 255) / 256, 256>>>(W1, bhi, blo);
    gemm_mma_kernel<128, 128><<<GB, 256, S1>>>(x, bhi, blo, H, n);
    aggregate_kernel<32, 1><<<(n + 7) / 8, 256>>>(H, rowptr, esw, dinv, b1, A, n);

    // --- layer 2: 128 -> 64 ---
    bprep_kernel<128, 64><<<(128 * 64 + 255) / 256, 256>>>(W2, bhi, blo);
    gemm_mma_kernel<128, 64><<<GB, 256, S2>>>(A, bhi, blo, H, n);
    aggregate_kernel<16, 1><<<(n + 15) / 16, 256>>>(H, rowptr, esw, dinv, b2, A, n);

    // --- layer 3: 64 -> 64 ---
    bprep_kernel<64, 64><<<(64 * 64 + 255) / 256, 256>>>(W3, bhi, blo);
    gemm_mma_kernel<64, 64><<<GB, 256, S3>>>(A, bhi, blo, H, n);
    aggregate_kernel<16, 0><<<(n + 15) / 16, 256>>>(H, rowptr, esw, dinv, b3,
                                                    (float*)d_out, n);
}